// round 6
// baseline (speedup 1.0000x reference)
#include <cuda_runtime.h>
#include <cuda_bf16.h>
#include <cstdint>
#include <math.h>

#define NN 100000
#define EE 1000000
#define DD 128
#define KK 256

#define BM 64
#define THREADS 1024
#define NBLK ((NN + BM - 1) / BM)     // 1563
#define WS_FLOATS (KK * DD)            // 32768 floats = 128 KB

// Scratch
__device__ int  g_cnt[NN];
__device__ int  g_off[NN];
__device__ int  g_cur[NN];
__device__ int  g_total;
__device__ int2 g_meta[EE];            // {src, w_as_int}

typedef unsigned long long u64;
typedef unsigned int u32;

// ---------------------------------------------------------------------------
// CSR build
// ---------------------------------------------------------------------------
__global__ void hist_kernel(const int* __restrict__ dst, int* __restrict__ cnt)
{
    int e = blockIdx.x * blockDim.x + threadIdx.x;
    if (e < EE) atomicAdd(&cnt[__ldg(dst + e)], 1);
}

__global__ void alloc_kernel(const int* __restrict__ cnt,
                             int* __restrict__ off,
                             int* __restrict__ cur,
                             int* __restrict__ total)
{
    int i = blockIdx.x * blockDim.x + threadIdx.x;
    if (i < NN) {
        int o = atomicAdd(total, cnt[i]);
        off[i] = o;
        cur[i] = o;
    }
}

__global__ void scatter_kernel(const int* __restrict__ src,
                               const int* __restrict__ dst,
                               const float* __restrict__ norm,
                               int* __restrict__ cur,
                               int2* __restrict__ meta)
{
    int e = blockIdx.x * blockDim.x + threadIdx.x;
    if (e >= EE) return;
    int s = __ldg(src + e);
    int d = __ldg(dst + e);
    float w = __ldg(norm + s) * __ldg(norm + d);
    int pos = atomicAdd(&cur[d], 1);
    meta[pos] = make_int2(s, __float_as_int(w));
}

// ---------------------------------------------------------------------------
// packed f32x2 helpers
// ---------------------------------------------------------------------------
__device__ __forceinline__ u64 dupf(float x)
{
    u64 r;
    u32 xi = __float_as_uint(x);
    asm("mov.b64 %0, {%1, %1};" : "=l"(r) : "r"(xi));
    return r;
}
__device__ __forceinline__ u64 mul2(u64 a, u64 b)
{
    u64 r; asm("mul.rn.f32x2 %0, %1, %2;" : "=l"(r) : "l"(a), "l"(b)); return r;
}
__device__ __forceinline__ u64 add2(u64 a, u64 b)
{
    u64 r; asm("add.rn.f32x2 %0, %1, %2;" : "=l"(r) : "l"(a), "l"(b)); return r;
}
__device__ __forceinline__ void fma2(u64& acc, u64 a, u64 b)
{
    asm("fma.rn.f32x2 %0, %1, %2, %0;" : "+l"(acc) : "l"(a), "l"(b));
}
__device__ __forceinline__ void unpack2(u64 v, float& lo, float& hi)
{
    u32 l, h;
    asm("mov.b64 {%0, %1}, %2;" : "=r"(l), "=r"(h) : "l"(v));
    lo = __uint_as_float(l);
    hi = __uint_as_float(h);
}
__device__ __forceinline__ void cp_async16(u32 dst, const void* src)
{
    asm volatile("cp.async.cg.shared.global [%0], [%1], 16;"
                 :: "r"(dst), "l"(src) : "memory");
}
#define COMP(v,i) ((i)==0 ? (v).x : (i)==1 ? (v).y : (i)==2 ? (v).z : (v).w)

// ---------------------------------------------------------------------------
// Fused: per-warp aggregate of 2 nodes (X kept in registers) -> per-warp GEMM
// via shfl x-broadcast + Ws in SMEM -> leaky + L2 norm -> store.
// No block barrier between aggregate and GEMM (only after the Ws cp.async).
// ---------------------------------------------------------------------------
__global__ void __launch_bounds__(THREADS, 1)
fused_kernel(const ulonglong2* __restrict__ egoq,
             const int*   __restrict__ off,
             const int*   __restrict__ cnt,
             const int2*  __restrict__ meta,
             const float* __restrict__ W1,
             const float* __restrict__ W2,
             float*       __restrict__ out)
{
    extern __shared__ float smem[];
    float* Ws = smem;                   // [256][128] = 128 KB

    const int tid  = threadIdx.x;
    const int lane = tid & 31;
    const int warp = tid >> 5;
    const int rowBase = blockIdx.x * BM;

    // ---- 1) async load W = [W1;W2] into SMEM
    {
        u32 wsBase;
        asm("{ .reg .u64 t; cvta.to.shared.u64 t, %1; cvt.u32.u64 %0, t; }"
            : "=r"(wsBase) : "l"(Ws));
        const float4* W1v = (const float4*)W1;
        const float4* W2v = (const float4*)W2;
        #pragma unroll
        for (int i = 0; i < 8; ++i) {
            int m  = tid + i * THREADS;     // 0..8191 float4
            int k  = m >> 5;
            int j4 = m & 31;
            const void* src = (k < DD) ? (const void*)&W1v[(size_t)k * 32 + j4]
                                       : (const void*)&W2v[(size_t)(k - DD) * 32 + j4];
            cp_async16(wsBase + m * 16, src);
        }
        asm volatile("cp.async.commit_group;" ::: "memory");
        asm volatile("cp.async.wait_group 0;" ::: "memory");
    }
    __syncthreads();   // the only block barrier

    // ---- 2) aggregate 2 nodes into packed registers
    float4 vA[2], vB[2];     // per-node X rows (this lane's 4 features), A and B part

    #pragma unroll
    for (int q = 0; q < 2; ++q) {
        int node = rowBase + warp * 2 + q;
        bool valid = node < NN;

        ulonglong2 hd2 = valid ? __ldg(egoq + (size_t)node * 32 + lane)
                               : make_ulonglong2(0ull, 0ull);
        u64 aP0 = hd2.x, aP1 = hd2.y;    // a = hd (self term)
        u64 bP0 = 0ull,  bP1 = 0ull;

        int n  = valid ? __ldg(cnt + node) : 0;
        int e0 = valid ? __ldg(off + node) : 0;

        for (int c = 0; c < n; c += 32) {
            int lim = min(32, n - c);
            int2 mm = (lane < lim) ? __ldg(meta + e0 + c + lane)
                                   : make_int2(0, 0);
            int j = 0;
            for (; j + 4 <= lim; j += 4) {
                int s0 = __shfl_sync(0xffffffffu, mm.x, j + 0);
                int s1 = __shfl_sync(0xffffffffu, mm.x, j + 1);
                int s2 = __shfl_sync(0xffffffffu, mm.x, j + 2);
                int s3 = __shfl_sync(0xffffffffu, mm.x, j + 3);
                u64 w0 = dupf(__int_as_float(__shfl_sync(0xffffffffu, mm.y, j + 0)));
                u64 w1 = dupf(__int_as_float(__shfl_sync(0xffffffffu, mm.y, j + 1)));
                u64 w2 = dupf(__int_as_float(__shfl_sync(0xffffffffu, mm.y, j + 2)));
                u64 w3 = dupf(__int_as_float(__shfl_sync(0xffffffffu, mm.y, j + 3)));
                ulonglong2 h0 = __ldg(egoq + (size_t)s0 * 32 + lane);
                ulonglong2 h1 = __ldg(egoq + (size_t)s1 * 32 + lane);
                ulonglong2 h2 = __ldg(egoq + (size_t)s2 * 32 + lane);
                ulonglong2 h3 = __ldg(egoq + (size_t)s3 * 32 + lane);
                u64 t;
                t = mul2(w0, h0.x); aP0 = add2(aP0, t); fma2(bP0, t, hd2.x);
                t = mul2(w0, h0.y); aP1 = add2(aP1, t); fma2(bP1, t, hd2.y);
                t = mul2(w1, h1.x); aP0 = add2(aP0, t); fma2(bP0, t, hd2.x);
                t = mul2(w1, h1.y); aP1 = add2(aP1, t); fma2(bP1, t, hd2.y);
                t = mul2(w2, h2.x); aP0 = add2(aP0, t); fma2(bP0, t, hd2.x);
                t = mul2(w2, h2.y); aP1 = add2(aP1, t); fma2(bP1, t, hd2.y);
                t = mul2(w3, h3.x); aP0 = add2(aP0, t); fma2(bP0, t, hd2.x);
                t = mul2(w3, h3.y); aP1 = add2(aP1, t); fma2(bP1, t, hd2.y);
            }
            for (; j < lim; ++j) {
                int s0 = __shfl_sync(0xffffffffu, mm.x, j);
                u64 w0 = dupf(__int_as_float(__shfl_sync(0xffffffffu, mm.y, j)));
                ulonglong2 h0 = __ldg(egoq + (size_t)s0 * 32 + lane);
                u64 t;
                t = mul2(w0, h0.x); aP0 = add2(aP0, t); fma2(bP0, t, hd2.x);
                t = mul2(w0, h0.y); aP1 = add2(aP1, t); fma2(bP1, t, hd2.y);
            }
        }

        unpack2(aP0, vA[q].x, vA[q].y);
        unpack2(aP1, vA[q].z, vA[q].w);
        unpack2(bP0, vB[q].x, vB[q].y);
        unpack2(bP1, vB[q].z, vB[q].w);
    }

    // ---- 3) per-warp GEMM: 2 rows x 128 cols; x via shfl, W via LDS.128
    const ulonglong2* Wsq = (const ulonglong2*)Ws;   // 32 ulonglong2 per k-row

    u64 acc00 = 0ull, acc01 = 0ull;   // row0: col pairs (4l,4l+1),(4l+2,4l+3)
    u64 acc10 = 0ull, acc11 = 0ull;   // row1

    #pragma unroll 8
    for (int kb = 0; kb < 128; kb += 4) {
        int srcl = kb >> 2;
        #pragma unroll
        for (int i = 0; i < 4; ++i) {
            float x0 = __shfl_sync(0xffffffffu, COMP(vA[0], i), srcl);
            float x1 = __shfl_sync(0xffffffffu, COMP(vA[1], i), srcl);
            ulonglong2 wp = Wsq[(size_t)(kb + i) * 32 + lane];
            u64 xd0 = dupf(x0), xd1 = dupf(x1);
            fma2(acc00, xd0, wp.x); fma2(acc01, xd0, wp.y);
            fma2(acc10, xd1, wp.x); fma2(acc11, xd1, wp.y);
        }
    }
    #pragma unroll 8
    for (int kb = 0; kb < 128; kb += 4) {
        int srcl = kb >> 2;
        #pragma unroll
        for (int i = 0; i < 4; ++i) {
            float x0 = __shfl_sync(0xffffffffu, COMP(vB[0], i), srcl);
            float x1 = __shfl_sync(0xffffffffu, COMP(vB[1], i), srcl);
            ulonglong2 wp = Wsq[(size_t)(128 + kb + i) * 32 + lane];
            u64 xd0 = dupf(x0), xd1 = dupf(x1);
            fma2(acc00, xd0, wp.x); fma2(acc01, xd0, wp.y);
            fma2(acc10, xd1, wp.x); fma2(acc11, xd1, wp.y);
        }
    }

    // ---- 4) epilogue: leaky relu, row L2 norm (warp butterfly), store
    float4* out4 = (float4*)out;
    #pragma unroll
    for (int q = 0; q < 2; ++q) {
        float v[4];
        if (q == 0) { unpack2(acc00, v[0], v[1]); unpack2(acc01, v[2], v[3]); }
        else        { unpack2(acc10, v[0], v[1]); unpack2(acc11, v[2], v[3]); }
        float p = 0.f;
        #pragma unroll
        for (int j = 0; j < 4; ++j) {
            float t = v[j];
            t = (t >= 0.f) ? t : 0.2f * t;
            v[j] = t;
            p = fmaf(t, t, p);
        }
        #pragma unroll
        for (int o = 16; o > 0; o >>= 1)
            p += __shfl_xor_sync(0xffffffffu, p, o);

        int grow = rowBase + warp * 2 + q;
        if (grow < NN) {
            float inv = 1.0f / fmaxf(sqrtf(p), 1e-12f);
            out4[(size_t)grow * 32 + lane] =
                make_float4(v[0] * inv, v[1] * inv, v[2] * inv, v[3] * inv);
        }
    }
}

// ---------------------------------------------------------------------------
// Launch
// ---------------------------------------------------------------------------
extern "C" void kernel_launch(void* const* d_in, const int* in_sizes, int n_in,
                              void* d_out, int out_size)
{
    const float* ego  = (const float*)d_in[0];
    const float* norm = (const float*)d_in[1];
    const int*   src  = (const int*)d_in[2];
    const int*   dst  = (const int*)d_in[3];
    const float* W1   = (const float*)d_in[4];
    const float* W2   = (const float*)d_in[5];
    float* out = (float*)d_out;

    int*  cnt;   cudaGetSymbolAddress((void**)&cnt,   g_cnt);
    int*  off;   cudaGetSymbolAddress((void**)&off,   g_off);
    int*  cur;   cudaGetSymbolAddress((void**)&cur,   g_cur);
    int*  total; cudaGetSymbolAddress((void**)&total, g_total);
    int2* meta;  cudaGetSymbolAddress((void**)&meta,  g_meta);

    cudaMemsetAsync(cnt, 0, NN * sizeof(int));
    cudaMemsetAsync(total, 0, sizeof(int));
    hist_kernel<<<(EE + 255) / 256, 256>>>(dst, cnt);
    alloc_kernel<<<(NN + 255) / 256, 256>>>(cnt, off, cur, total);
    scatter_kernel<<<(EE + 255) / 256, 256>>>(src, dst, norm, cur, meta);

    int smem = WS_FLOATS * (int)sizeof(float);   // 128 KB
    cudaFuncSetAttribute(fused_kernel,
                         cudaFuncAttributeMaxDynamicSharedMemorySize, smem);
    fused_kernel<<<NBLK, THREADS, smem>>>(
        (const ulonglong2*)ego, off, cnt, meta, W1, W2, out);
}

// round 8
// speedup vs baseline: 1.7221x; 1.7221x over previous
#include <cuda_runtime.h>
#include <cuda_bf16.h>
#include <cstdint>
#include <math.h>

#define NN 100000
#define EE 1000000
#define BM 64
#define THREADS 512
#define NBLK ((NN + BM - 1) / BM)      // 1563

// B (W) padded layout: [256 k][144 n] bf16
#define BP 144
// X padded layout: [64 m][272 k] bf16
#define XP 272

// smem byte offsets
#define SM_B_HI   0
#define SM_B_LO   73728
#define SM_XHI    147456
#define SM_XLO    182272
#define SM_ROWSUM 217088
#define SM_TOTAL  217344

typedef unsigned int u32;
typedef unsigned long long u64;

// Scratch
__device__ int  g_cnt[NN];
__device__ int  g_off[NN];
__device__ int  g_cur[NN];
__device__ int  g_total;
__device__ int2 g_meta[EE];
__device__ __align__(16) __nv_bfloat16 g_Bhi[256 * BP];
__device__ __align__(16) __nv_bfloat16 g_Blo[256 * BP];

// ---------------------------------------------------------------------------
// CSR build
// ---------------------------------------------------------------------------
__global__ void hist_kernel(const int* __restrict__ dst, int* __restrict__ cnt)
{
    int e = blockIdx.x * blockDim.x + threadIdx.x;
    if (e < EE) atomicAdd(&cnt[__ldg(dst + e)], 1);
}

__global__ void alloc_kernel(const int* __restrict__ cnt,
                             int* __restrict__ off,
                             int* __restrict__ cur,
                             int* __restrict__ total)
{
    int i = blockIdx.x * blockDim.x + threadIdx.x;
    if (i < NN) {
        int o = atomicAdd(total, cnt[i]);
        off[i] = o;
        cur[i] = o;
    }
}

__global__ void scatter_kernel(const int* __restrict__ src,
                               const int* __restrict__ dst,
                               const float* __restrict__ norm,
                               int* __restrict__ cur,
                               int2* __restrict__ meta)
{
    int e = blockIdx.x * blockDim.x + threadIdx.x;
    if (e >= EE) return;
    int s = __ldg(src + e);
    int d = __ldg(dst + e);
    float w = __ldg(norm + s) * __ldg(norm + d);
    int pos = atomicAdd(&cur[d], 1);
    meta[pos] = make_int2(s, __float_as_int(w));
}

// ---------------------------------------------------------------------------
// B prep: W=[W1;W2] (k-major) -> bf16 hi/lo, padded rows
// ---------------------------------------------------------------------------
__global__ void prepB_kernel(const float* __restrict__ W1,
                             const float* __restrict__ W2,
                             __nv_bfloat16* __restrict__ bhi,
                             __nv_bfloat16* __restrict__ blo)
{
    int idx = blockIdx.x * blockDim.x + threadIdx.x;   // 256*128
    if (idx >= 256 * 128) return;
    int k = idx >> 7;
    int n = idx & 127;
    float v = (k < 128) ? __ldg(W1 + k * 128 + n) : __ldg(W2 + (k - 128) * 128 + n);
    __nv_bfloat16 h = __float2bfloat16(v);
    bhi[k * BP + n] = h;
    blo[k * BP + n] = __float2bfloat16(v - __bfloat162float(h));
}

// ---------------------------------------------------------------------------
// PTX helpers (portable: cp.async, ldmatrix, mma.sync)
// ---------------------------------------------------------------------------
__device__ __forceinline__ u32 smem_u32_of(const void* p)
{
    u32 a;
    asm("{ .reg .u64 t; cvta.to.shared.u64 t, %1; cvt.u32.u64 %0, t; }"
        : "=r"(a) : "l"(p));
    return a;
}
__device__ __forceinline__ void cp_async16(u32 dst, const void* src)
{
    asm volatile("cp.async.cg.shared.global [%0], [%1], 16;"
                 :: "r"(dst), "l"(src) : "memory");
}
__device__ __forceinline__ void ldsm_x4(u32& r0, u32& r1, u32& r2, u32& r3, u32 addr)
{
    asm volatile("ldmatrix.sync.aligned.m8n8.x4.shared.b16 {%0,%1,%2,%3}, [%4];"
                 : "=r"(r0), "=r"(r1), "=r"(r2), "=r"(r3) : "r"(addr));
}
__device__ __forceinline__ void ldsm_x4_t(u32& r0, u32& r1, u32& r2, u32& r3, u32 addr)
{
    asm volatile("ldmatrix.sync.aligned.m8n8.x4.trans.shared.b16 {%0,%1,%2,%3}, [%4];"
                 : "=r"(r0), "=r"(r1), "=r"(r2), "=r"(r3) : "r"(addr));
}
__device__ __forceinline__ void mma16816(float* c, u32 a0, u32 a1, u32 a2, u32 a3,
                                         u32 b0, u32 b1)
{
    asm volatile(
        "mma.sync.aligned.m16n8k16.row.col.f32.bf16.bf16.f32 "
        "{%0,%1,%2,%3}, {%4,%5,%6,%7}, {%8,%9}, {%0,%1,%2,%3};"
        : "+f"(c[0]), "+f"(c[1]), "+f"(c[2]), "+f"(c[3])
        : "r"(a0), "r"(a1), "r"(a2), "r"(a3), "r"(b0), "r"(b1));
}
__device__ __forceinline__ u32 pack_hi(float x, float y)
{
    unsigned short b0 = __bfloat16_as_ushort(__float2bfloat16(x));
    unsigned short b1 = __bfloat16_as_ushort(__float2bfloat16(y));
    return (u32)b0 | ((u32)b1 << 16);
}
__device__ __forceinline__ u32 pack_lo(float x, float y)
{
    float hx = __bfloat162float(__float2bfloat16(x));
    float hy = __bfloat162float(__float2bfloat16(y));
    unsigned short b0 = __bfloat16_as_ushort(__float2bfloat16(x - hx));
    unsigned short b1 = __bfloat16_as_ushort(__float2bfloat16(y - hy));
    return (u32)b0 | ((u32)b1 << 16);
}

// ---------------------------------------------------------------------------
// Fused: cp.async B || aggregate -> Xhi/Xlo smem -> mma.sync GEMM (split-2)
// -> leaky + row L2 norm -> store
// ---------------------------------------------------------------------------
__global__ void __launch_bounds__(THREADS, 1)
fused_kernel(const float4* __restrict__ ego,
             const int*   __restrict__ off,
             const int*   __restrict__ cnt,
             const int2*  __restrict__ meta,
             float*       __restrict__ out)
{
    extern __shared__ char smem[];
    const u32 smem_base = smem_u32_of(smem);
    float* rowsum = (float*)(smem + SM_ROWSUM);

    const int tid  = threadIdx.x;
    const int lane = tid & 31;
    const int warp = tid >> 5;
    const int rowBase = blockIdx.x * BM;

    // ---- 1) issue cp.async of Bhi/Blo (147 KB), fire and forget
    {
        const char* shi = (const char*)g_Bhi;
        const char* slo = (const char*)g_Blo;
        #pragma unroll
        for (int i = 0; i < 9; ++i) {
            int m = tid + i * THREADS;              // 0..4607 chunks of 16B
            cp_async16(smem_base + SM_B_HI + m * 16, shi + m * 16);
            cp_async16(smem_base + SM_B_LO + m * 16, slo + m * 16);
        }
        asm volatile("cp.async.commit_group;" ::: "memory");
    }
    if (tid < BM) rowsum[tid] = 0.f;

    // ---- 2) aggregate 4 nodes per warp -> Xhi/Xlo smem (bf16)
    for (int q = 0; q < 4; ++q) {
        int r = warp * 4 + q;
        int node = rowBase + r;
        bool valid = node < NN;

        float4 hd = valid ? __ldg(ego + (size_t)node * 32 + lane)
                          : make_float4(0.f, 0.f, 0.f, 0.f);
        float4 a = hd;
        float4 b = make_float4(0.f, 0.f, 0.f, 0.f);

        int n  = valid ? __ldg(cnt + node) : 0;
        int e0 = valid ? __ldg(off + node) : 0;

        for (int c = 0; c < n; c += 32) {
            int lim = min(32, n - c);
            int2 mm = (lane < lim) ? __ldg(meta + e0 + c + lane) : make_int2(0, 0);
            int j = 0;
            for (; j + 4 <= lim; j += 4) {
                int   s0 = __shfl_sync(0xffffffffu, mm.x, j + 0);
                int   s1 = __shfl_sync(0xffffffffu, mm.x, j + 1);
                int   s2 = __shfl_sync(0xffffffffu, mm.x, j + 2);
                int   s3 = __shfl_sync(0xffffffffu, mm.x, j + 3);
                float w0 = __int_as_float(__shfl_sync(0xffffffffu, mm.y, j + 0));
                float w1 = __int_as_float(__shfl_sync(0xffffffffu, mm.y, j + 1));
                float w2 = __int_as_float(__shfl_sync(0xffffffffu, mm.y, j + 2));
                float w3 = __int_as_float(__shfl_sync(0xffffffffu, mm.y, j + 3));
                float4 h0 = __ldg(ego + (size_t)s0 * 32 + lane);
                float4 h1 = __ldg(ego + (size_t)s1 * 32 + lane);
                float4 h2 = __ldg(ego + (size_t)s2 * 32 + lane);
                float4 h3 = __ldg(ego + (size_t)s3 * 32 + lane);
                float t;
                t = w0 * h0.x; a.x += t; b.x = fmaf(t, hd.x, b.x);
                t = w0 * h0.y; a.y += t; b.y = fmaf(t, hd.y, b.y);
                t = w0 * h0.z; a.z += t; b.z = fmaf(t, hd.z, b.z);
                t = w0 * h0.w; a.w += t; b.w = fmaf(t, hd.w, b.w);
                t = w1 * h1.x; a.x += t; b.x = fmaf(t, hd.x, b.x);
                t = w1 * h1.y; a.y += t; b.y = fmaf(t, hd.y, b.y);
                t = w1 * h1.z; a.z += t; b.z = fmaf(t, hd.z, b.z);
                t = w1 * h1.w; a.w += t; b.w = fmaf(t, hd.w, b.w);
                t = w2 * h2.x; a.x += t; b.x = fmaf(t, hd.x, b.x);
                t = w2 * h2.y; a.y += t; b.y = fmaf(t, hd.y, b.y);
                t = w2 * h2.z; a.z += t; b.z = fmaf(t, hd.z, b.z);
                t = w2 * h2.w; a.w += t; b.w = fmaf(t, hd.w, b.w);
                t = w3 * h3.x; a.x += t; b.x = fmaf(t, hd.x, b.x);
                t = w3 * h3.y; a.y += t; b.y = fmaf(t, hd.y, b.y);
                t = w3 * h3.z; a.z += t; b.z = fmaf(t, hd.z, b.z);
                t = w3 * h3.w; a.w += t; b.w = fmaf(t, hd.w, b.w);
            }
            for (; j < lim; ++j) {
                int   s0 = __shfl_sync(0xffffffffu, mm.x, j);
                float w0 = __int_as_float(__shfl_sync(0xffffffffu, mm.y, j));
                float4 h0 = __ldg(ego + (size_t)s0 * 32 + lane);
                float t;
                t = w0 * h0.x; a.x += t; b.x = fmaf(t, hd.x, b.x);
                t = w0 * h0.y; a.y += t; b.y = fmaf(t, hd.y, b.y);
                t = w0 * h0.z; a.z += t; b.z = fmaf(t, hd.z, b.z);
                t = w0 * h0.w; a.w += t; b.w = fmaf(t, hd.w, b.w);
            }
        }

        // X row r: k = lane*4 (A part), k = 128 + lane*4 (B part)
        u32* xh = (u32*)(smem + SM_XHI + (size_t)r * (XP * 2));
        u32* xl = (u32*)(smem + SM_XLO + (size_t)r * (XP * 2));
        xh[lane * 2 + 0]  = pack_hi(a.x, a.y);
        xh[lane * 2 + 1]  = pack_hi(a.z, a.w);
        xh[64 + lane * 2] = pack_hi(b.x, b.y);
        xh[65 + lane * 2] = pack_hi(b.z, b.w);
        xl[lane * 2 + 0]  = pack_lo(a.x, a.y);
        xl[lane * 2 + 1]  = pack_lo(a.z, a.w);
        xl[64 + lane * 2] = pack_lo(b.x, b.y);
        xl[65 + lane * 2] = pack_lo(b.z, b.w);
    }

    asm volatile("cp.async.wait_group 0;" ::: "memory");
    __syncthreads();

    // ---- 3) GEMM: warps as 4m x 4n grid; warp tile 16m x 32n; K=256
    const int m0 = (warp >> 2) * 16;
    const int n0 = (warp & 3) * 32;

    float acc[4][4];
    #pragma unroll
    for (int i = 0; i < 4; ++i)
        #pragma unroll
        for (int j = 0; j < 4; ++j) acc[i][j] = 0.f;

    // per-lane ldmatrix addresses
    const u32 a_row = m0 + (lane & 15);
    const u32 a_col = (lane >> 4) * 8;                 // + k0
    const u32 aHiBase = smem_base + SM_XHI + a_row * (XP * 2) + a_col * 2;
    const u32 aLoBase = smem_base + SM_XLO + a_row * (XP * 2) + a_col * 2;
    const u32 b_krow = (lane & 7) + ((lane >> 3) & 1) * 8;   // + k0
    const u32 b_ncol = (lane >> 4) * 8;                      // + n0 (+16)
    const u32 bHiBase = smem_base + SM_B_HI + b_krow * (BP * 2) + (n0 + b_ncol) * 2;
    const u32 bLoBase = smem_base + SM_B_LO + b_krow * (BP * 2) + (n0 + b_ncol) * 2;

    #pragma unroll 4
    for (int ks = 0; ks < 16; ++ks) {
        const u32 kOffA = ks * 32;                     // 16 bf16 = 32 B
        const u32 kOffB = ks * 16 * (BP * 2);
        u32 ah0, ah1, ah2, ah3, al0, al1, al2, al3;
        ldsm_x4(ah0, ah1, ah2, ah3, aHiBase + kOffA);
        ldsm_x4(al0, al1, al2, al3, aLoBase + kOffA);

        u32 bh0, bh1, bh2, bh3, bl0, bl1, bl2, bl3;
        // n-tiles 0,1 (n0 .. n0+15)
        ldsm_x4_t(bh0, bh1, bh2, bh3, bHiBase + kOffB);
        ldsm_x4_t(bl0, bl1, bl2, bl3, bLoBase + kOffB);
        mma16816(acc[0], ah0, ah1, ah2, ah3, bh0, bh1);
        mma16816(acc[0], ah0, ah1, ah2, ah3, bl0, bl1);
        mma16816(acc[0], al0, al1, al2, al3, bh0, bh1);
        mma16816(acc[1], ah0, ah1, ah2, ah3, bh2, bh3);
        mma16816(acc[1], ah0, ah1, ah2, ah3, bl2, bl3);
        mma16816(acc[1], al0, al1, al2, al3, bh2, bh3);
        // n-tiles 2,3 (n0+16 .. n0+31)
        ldsm_x4_t(bh0, bh1, bh2, bh3, bHiBase + kOffB + 32);
        ldsm_x4_t(bl0, bl1, bl2, bl3, bLoBase + kOffB + 32);
        mma16816(acc[2], ah0, ah1, ah2, ah3, bh0, bh1);
        mma16816(acc[2], ah0, ah1, ah2, ah3, bl0, bl1);
        mma16816(acc[2], al0, al1, al2, al3, bh0, bh1);
        mma16816(acc[3], ah0, ah1, ah2, ah3, bh2, bh3);
        mma16816(acc[3], ah0, ah1, ah2, ah3, bl2, bl3);
        mma16816(acc[3], al0, al1, al2, al3, bh2, bh3);
    }

    // ---- 4) leaky relu + per-row sumsq partials
    float p0 = 0.f, p1 = 0.f;
    #pragma unroll
    for (int nt = 0; nt < 4; ++nt) {
        #pragma unroll
        for (int j = 0; j < 4; ++j) {
            float v = acc[nt][j];
            v = (v >= 0.f) ? v : 0.2f * v;
            acc[nt][j] = v;
            if (j < 2) p0 = fmaf(v, v, p0);
            else       p1 = fmaf(v, v, p1);
        }
    }
    p0 += __shfl_xor_sync(0xffffffffu, p0, 1);
    p0 += __shfl_xor_sync(0xffffffffu, p0, 2);
    p1 += __shfl_xor_sync(0xffffffffu, p1, 1);
    p1 += __shfl_xor_sync(0xffffffffu, p1, 2);

    const int r0 = m0 + (lane >> 2);
    const int r1 = r0 + 8;
    if ((lane & 3) == 0) {
        atomicAdd(rowsum + r0, p0);
        atomicAdd(rowsum + r1, p1);
    }
    __syncthreads();

    // ---- 5) scale + store
    const float inv0 = 1.0f / fmaxf(sqrtf(rowsum[r0]), 1e-12f);
    const float inv1 = 1.0f / fmaxf(sqrtf(rowsum[r1]), 1e-12f);
    float2* out2 = (float2*)out;
    const int g0 = rowBase + r0;
    const int g1 = rowBase + r1;
    const int colh = (n0 + (lane & 3) * 2) >> 1;       // float2 index base within row
    #pragma unroll
    for (int nt = 0; nt < 4; ++nt) {
        int c2 = colh + nt * 4;                        // + nt*8 cols
        if (g0 < NN)
            out2[(size_t)g0 * 64 + c2] = make_float2(acc[nt][0] * inv0, acc[nt][1] * inv0);
        if (g1 < NN)
            out2[(size_t)g1 * 64 + c2] = make_float2(acc[nt][2] * inv1, acc[nt][3] * inv1);
    }
}

// ---------------------------------------------------------------------------
// Launch
// ---------------------------------------------------------------------------
extern "C" void kernel_launch(void* const* d_in, const int* in_sizes, int n_in,
                              void* d_out, int out_size)
{
    const float* ego  = (const float*)d_in[0];
    const float* norm = (const float*)d_in[1];
    const int*   src  = (const int*)d_in[2];
    const int*   dst  = (const int*)d_in[3];
    const float* W1   = (const float*)d_in[4];
    const float* W2   = (const float*)d_in[5];
    float* out = (float*)d_out;

    int*  cnt;   cudaGetSymbolAddress((void**)&cnt,   g_cnt);
    int*  off;   cudaGetSymbolAddress((void**)&off,   g_off);
    int*  cur;   cudaGetSymbolAddress((void**)&cur,   g_cur);
    int*  total; cudaGetSymbolAddress((void**)&total, g_total);
    int2* meta;  cudaGetSymbolAddress((void**)&meta,  g_meta);
    __nv_bfloat16* bhi; cudaGetSymbolAddress((void**)&bhi, g_Bhi);
    __nv_bfloat16* blo; cudaGetSymbolAddress((void**)&blo, g_Blo);

    cudaMemsetAsync(cnt, 0, NN * sizeof(int));
    cudaMemsetAsync(total, 0, sizeof(int));
    hist_kernel<<<(EE + 255) / 256, 256>>>(dst, cnt);
    alloc_kernel<<<(NN + 255) / 256, 256>>>(cnt, off, cur, total);
    scatter_kernel<<<(EE + 255) / 256, 256>>>(src, dst, norm, cur, meta);
    prepB_kernel<<<128, 256>>>(W1, W2, bhi, blo);

    cudaFuncSetAttribute(fused_kernel,
                         cudaFuncAttributeMaxDynamicSharedMemorySize, SM_TOTAL);
    fused_kernel<<<NBLK, THREADS, SM_TOTAL>>>(
        (const float4*)ego, off, cnt, meta, out);
}

// round 9
// speedup vs baseline: 1.7555x; 1.0194x over previous
#include <cuda_runtime.h>
#include <cuda_bf16.h>
#include <cstdint>
#include <math.h>

#define NN 100000
#define EE 1000000
#define BM 64
#define THREADS 512
#define NBLK ((NN + BM - 1) / BM)      // 1563
#define GRID_PERSIST 148

// B (W) padded layout: [256 k][144 n] bf16
#define BP 144
// X padded layout: [64 m][272 k] bf16
#define XP 272

// smem byte offsets
#define SM_B_HI   0
#define SM_B_LO   73728
#define SM_XHI    147456
#define SM_XLO    182272
#define SM_ROWSUM 217088
#define SM_TOTAL  217344

typedef unsigned int u32;
typedef unsigned long long u64;

// Scratch
__device__ int  g_cnt[NN];
__device__ int  g_off[NN];
__device__ int  g_cur[NN];
__device__ int  g_total;
__device__ int2 g_meta[EE];
__device__ __align__(16) __nv_bfloat16 g_Bhi[256 * BP];
__device__ __align__(16) __nv_bfloat16 g_Blo[256 * BP];

// ---------------------------------------------------------------------------
// CSR build
// ---------------------------------------------------------------------------
__global__ void hist_kernel(const int* __restrict__ dst, int* __restrict__ cnt)
{
    int e = blockIdx.x * blockDim.x + threadIdx.x;
    if (e < EE) atomicAdd(&cnt[__ldg(dst + e)], 1);
}

__global__ void alloc_kernel(const int* __restrict__ cnt,
                             int* __restrict__ off,
                             int* __restrict__ cur,
                             int* __restrict__ total)
{
    int i = blockIdx.x * blockDim.x + threadIdx.x;
    if (i < NN) {
        int o = atomicAdd(total, cnt[i]);
        off[i] = o;
        cur[i] = o;
    }
}

__global__ void scatter_kernel(const int* __restrict__ src,
                               const int* __restrict__ dst,
                               const float* __restrict__ norm,
                               int* __restrict__ cur,
                               int2* __restrict__ meta)
{
    int e = blockIdx.x * blockDim.x + threadIdx.x;
    if (e >= EE) return;
    int s = __ldg(src + e);
    int d = __ldg(dst + e);
    float w = __ldg(norm + s) * __ldg(norm + d);
    int pos = atomicAdd(&cur[d], 1);
    meta[pos] = make_int2(s, __float_as_int(w));
}

// ---------------------------------------------------------------------------
// B prep: W=[W1;W2] (k-major) -> bf16 hi/lo, padded rows
// ---------------------------------------------------------------------------
__global__ void prepB_kernel(const float* __restrict__ W1,
                             const float* __restrict__ W2,
                             __nv_bfloat16* __restrict__ bhi,
                             __nv_bfloat16* __restrict__ blo)
{
    int idx = blockIdx.x * blockDim.x + threadIdx.x;   // 256*128
    if (idx >= 256 * 128) return;
    int k = idx >> 7;
    int n = idx & 127;
    float v = (k < 128) ? __ldg(W1 + k * 128 + n) : __ldg(W2 + (k - 128) * 128 + n);
    __nv_bfloat16 h = __float2bfloat16(v);
    bhi[k * BP + n] = h;
    blo[k * BP + n] = __float2bfloat16(v - __bfloat162float(h));
}

// ---------------------------------------------------------------------------
// PTX helpers (portable: cp.async, ldmatrix, mma.sync)
// ---------------------------------------------------------------------------
__device__ __forceinline__ u32 smem_u32_of(const void* p)
{
    u32 a;
    asm("{ .reg .u64 t; cvta.to.shared.u64 t, %1; cvt.u32.u64 %0, t; }"
        : "=r"(a) : "l"(p));
    return a;
}
__device__ __forceinline__ void cp_async16(u32 dst, const void* src)
{
    asm volatile("cp.async.cg.shared.global [%0], [%1], 16;"
                 :: "r"(dst), "l"(src) : "memory");
}
__device__ __forceinline__ void ldsm_x4(u32& r0, u32& r1, u32& r2, u32& r3, u32 addr)
{
    asm volatile("ldmatrix.sync.aligned.m8n8.x4.shared.b16 {%0,%1,%2,%3}, [%4];"
                 : "=r"(r0), "=r"(r1), "=r"(r2), "=r"(r3) : "r"(addr));
}
__device__ __forceinline__ void ldsm_x4_t(u32& r0, u32& r1, u32& r2, u32& r3, u32 addr)
{
    asm volatile("ldmatrix.sync.aligned.m8n8.x4.trans.shared.b16 {%0,%1,%2,%3}, [%4];"
                 : "=r"(r0), "=r"(r1), "=r"(r2), "=r"(r3) : "r"(addr));
}
__device__ __forceinline__ void mma16816(float* c, u32 a0, u32 a1, u32 a2, u32 a3,
                                         u32 b0, u32 b1)
{
    asm volatile(
        "mma.sync.aligned.m16n8k16.row.col.f32.bf16.bf16.f32 "
        "{%0,%1,%2,%3}, {%4,%5,%6,%7}, {%8,%9}, {%0,%1,%2,%3};"
        : "+f"(c[0]), "+f"(c[1]), "+f"(c[2]), "+f"(c[3])
        : "r"(a0), "r"(a1), "r"(a2), "r"(a3), "r"(b0), "r"(b1));
}
__device__ __forceinline__ u32 pack_hi(float x, float y)
{
    unsigned short b0 = __bfloat16_as_ushort(__float2bfloat16(x));
    unsigned short b1 = __bfloat16_as_ushort(__float2bfloat16(y));
    return (u32)b0 | ((u32)b1 << 16);
}
__device__ __forceinline__ u32 pack_lo(float x, float y)
{
    float hx = __bfloat162float(__float2bfloat16(x));
    float hy = __bfloat162float(__float2bfloat16(y));
    unsigned short b0 = __bfloat16_as_ushort(__float2bfloat16(x - hx));
    unsigned short b1 = __bfloat16_as_ushort(__float2bfloat16(y - hy));
    return (u32)b0 | ((u32)b1 << 16);
}

// ---------------------------------------------------------------------------
// Persistent fused kernel: load B once, loop over 64-node tiles:
// aggregate -> Xhi/Xlo smem -> mma.sync split-2 GEMM -> leaky + L2 norm -> out
// ---------------------------------------------------------------------------
__global__ void __launch_bounds__(THREADS, 1)
fused_kernel(const float4* __restrict__ ego,
             const int*   __restrict__ off,
             const int*   __restrict__ cnt,
             const int2*  __restrict__ meta,
             float*       __restrict__ out)
{
    extern __shared__ char smem[];
    const u32 smem_base = smem_u32_of(smem);
    float* rowsum = (float*)(smem + SM_ROWSUM);

    const int tid  = threadIdx.x;
    const int lane = tid & 31;
    const int warp = tid >> 5;

    // ---- 0) one-time: load Bhi/Blo (294 KB) into smem
    {
        const char* shi = (const char*)g_Bhi;
        const char* slo = (const char*)g_Blo;
        #pragma unroll
        for (int i = 0; i < 9; ++i) {
            int m = tid + i * THREADS;
            cp_async16(smem_base + SM_B_HI + m * 16, shi + m * 16);
            cp_async16(smem_base + SM_B_LO + m * 16, slo + m * 16);
        }
        asm volatile("cp.async.commit_group;" ::: "memory");
        asm volatile("cp.async.wait_group 0;" ::: "memory");
    }
    if (tid < BM) rowsum[tid] = 0.f;
    __syncthreads();

    // GEMM constants (per-lane ldmatrix addressing)
    const int m0 = (warp >> 2) * 16;
    const int n0 = (warp & 3) * 32;
    const u32 a_row = m0 + (lane & 15);
    const u32 a_col = (lane >> 4) * 8;
    const u32 aHiBase = smem_base + SM_XHI + a_row * (XP * 2) + a_col * 2;
    const u32 aLoBase = smem_base + SM_XLO + a_row * (XP * 2) + a_col * 2;
    const u32 b_krow = (lane & 7) + ((lane >> 3) & 1) * 8;
    const u32 b_ncol = (lane >> 4) * 8;
    const u32 bHiBase = smem_base + SM_B_HI + b_krow * (BP * 2) + (n0 + b_ncol) * 2;
    const u32 bLoBase = smem_base + SM_B_LO + b_krow * (BP * 2) + (n0 + b_ncol) * 2;
    const int r0 = m0 + (lane >> 2);
    const int r1 = r0 + 8;

    for (int tile = blockIdx.x; tile < NBLK; tile += GRID_PERSIST) {
        const int rowBase = tile * BM;

        // ---- 1) aggregate 4 nodes per warp -> Xhi/Xlo smem (bf16)
        for (int q = 0; q < 4; ++q) {
            int r = warp * 4 + q;
            int node = rowBase + r;
            bool valid = node < NN;

            float4 hd = valid ? __ldg(ego + (size_t)node * 32 + lane)
                              : make_float4(0.f, 0.f, 0.f, 0.f);
            float4 a = hd;
            float4 b = make_float4(0.f, 0.f, 0.f, 0.f);

            int n  = valid ? __ldg(cnt + node) : 0;
            int e0 = valid ? __ldg(off + node) : 0;

            for (int c = 0; c < n; c += 32) {
                int lim = min(32, n - c);
                int2 mm = (lane < lim) ? __ldg(meta + e0 + c + lane) : make_int2(0, 0);
                int j = 0;
                for (; j + 4 <= lim; j += 4) {
                    int   s0 = __shfl_sync(0xffffffffu, mm.x, j + 0);
                    int   s1 = __shfl_sync(0xffffffffu, mm.x, j + 1);
                    int   s2 = __shfl_sync(0xffffffffu, mm.x, j + 2);
                    int   s3 = __shfl_sync(0xffffffffu, mm.x, j + 3);
                    float w0 = __int_as_float(__shfl_sync(0xffffffffu, mm.y, j + 0));
                    float w1 = __int_as_float(__shfl_sync(0xffffffffu, mm.y, j + 1));
                    float w2 = __int_as_float(__shfl_sync(0xffffffffu, mm.y, j + 2));
                    float w3 = __int_as_float(__shfl_sync(0xffffffffu, mm.y, j + 3));
                    float4 h0 = __ldg(ego + (size_t)s0 * 32 + lane);
                    float4 h1 = __ldg(ego + (size_t)s1 * 32 + lane);
                    float4 h2 = __ldg(ego + (size_t)s2 * 32 + lane);
                    float4 h3 = __ldg(ego + (size_t)s3 * 32 + lane);
                    float t;
                    t = w0 * h0.x; a.x += t; b.x = fmaf(t, hd.x, b.x);
                    t = w0 * h0.y; a.y += t; b.y = fmaf(t, hd.y, b.y);
                    t = w0 * h0.z; a.z += t; b.z = fmaf(t, hd.z, b.z);
                    t = w0 * h0.w; a.w += t; b.w = fmaf(t, hd.w, b.w);
                    t = w1 * h1.x; a.x += t; b.x = fmaf(t, hd.x, b.x);
                    t = w1 * h1.y; a.y += t; b.y = fmaf(t, hd.y, b.y);
                    t = w1 * h1.z; a.z += t; b.z = fmaf(t, hd.z, b.z);
                    t = w1 * h1.w; a.w += t; b.w = fmaf(t, hd.w, b.w);
                    t = w2 * h2.x; a.x += t; b.x = fmaf(t, hd.x, b.x);
                    t = w2 * h2.y; a.y += t; b.y = fmaf(t, hd.y, b.y);
                    t = w2 * h2.z; a.z += t; b.z = fmaf(t, hd.z, b.z);
                    t = w2 * h2.w; a.w += t; b.w = fmaf(t, hd.w, b.w);
                    t = w3 * h3.x; a.x += t; b.x = fmaf(t, hd.x, b.x);
                    t = w3 * h3.y; a.y += t; b.y = fmaf(t, hd.y, b.y);
                    t = w3 * h3.z; a.z += t; b.z = fmaf(t, hd.z, b.z);
                    t = w3 * h3.w; a.w += t; b.w = fmaf(t, hd.w, b.w);
                }
                for (; j < lim; ++j) {
                    int   s0 = __shfl_sync(0xffffffffu, mm.x, j);
                    float w0 = __int_as_float(__shfl_sync(0xffffffffu, mm.y, j));
                    float4 h0 = __ldg(ego + (size_t)s0 * 32 + lane);
                    float t;
                    t = w0 * h0.x; a.x += t; b.x = fmaf(t, hd.x, b.x);
                    t = w0 * h0.y; a.y += t; b.y = fmaf(t, hd.y, b.y);
                    t = w0 * h0.z; a.z += t; b.z = fmaf(t, hd.z, b.z);
                    t = w0 * h0.w; a.w += t; b.w = fmaf(t, hd.w, b.w);
                }
            }

            u32* xh = (u32*)(smem + SM_XHI + (size_t)r * (XP * 2));
            u32* xl = (u32*)(smem + SM_XLO + (size_t)r * (XP * 2));
            xh[lane * 2 + 0]  = pack_hi(a.x, a.y);
            xh[lane * 2 + 1]  = pack_hi(a.z, a.w);
            xh[64 + lane * 2] = pack_hi(b.x, b.y);
            xh[65 + lane * 2] = pack_hi(b.z, b.w);
            xl[lane * 2 + 0]  = pack_lo(a.x, a.y);
            xl[lane * 2 + 1]  = pack_lo(a.z, a.w);
            xl[64 + lane * 2] = pack_lo(b.x, b.y);
            xl[65 + lane * 2] = pack_lo(b.z, b.w);
        }
        __syncthreads();

        // ---- 2) GEMM: warps 4m x 4n; warp tile 16m x 32n; K=256, split-2
        float acc[4][4];
        #pragma unroll
        for (int i = 0; i < 4; ++i)
            #pragma unroll
            for (int j = 0; j < 4; ++j) acc[i][j] = 0.f;

        #pragma unroll 4
        for (int ks = 0; ks < 16; ++ks) {
            const u32 kOffA = ks * 32;
            const u32 kOffB = ks * 16 * (BP * 2);
            u32 ah0, ah1, ah2, ah3, al0, al1, al2, al3;
            ldsm_x4(ah0, ah1, ah2, ah3, aHiBase + kOffA);
            ldsm_x4(al0, al1, al2, al3, aLoBase + kOffA);

            u32 bh0, bh1, bh2, bh3, bl0, bl1, bl2, bl3;
            ldsm_x4_t(bh0, bh1, bh2, bh3, bHiBase + kOffB);
            ldsm_x4_t(bl0, bl1, bl2, bl3, bLoBase + kOffB);
            mma16816(acc[0], ah0, ah1, ah2, ah3, bh0, bh1);
            mma16816(acc[0], ah0, ah1, ah2, ah3, bl0, bl1);
            mma16816(acc[0], al0, al1, al2, al3, bh0, bh1);
            mma16816(acc[1], ah0, ah1, ah2, ah3, bh2, bh3);
            mma16816(acc[1], ah0, ah1, ah2, ah3, bl2, bl3);
            mma16816(acc[1], al0, al1, al2, al3, bh2, bh3);
            ldsm_x4_t(bh0, bh1, bh2, bh3, bHiBase + kOffB + 32);
            ldsm_x4_t(bl0, bl1, bl2, bl3, bLoBase + kOffB + 32);
            mma16816(acc[2], ah0, ah1, ah2, ah3, bh0, bh1);
            mma16816(acc[2], ah0, ah1, ah2, ah3, bl0, bl1);
            mma16816(acc[2], al0, al1, al2, al3, bh0, bh1);
            mma16816(acc[3], ah0, ah1, ah2, ah3, bh2, bh3);
            mma16816(acc[3], ah0, ah1, ah2, ah3, bl2, bl3);
            mma16816(acc[3], al0, al1, al2, al3, bh2, bh3);
        }

        // ---- 3) leaky relu + per-row sumsq partials
        float p0 = 0.f, p1 = 0.f;
        #pragma unroll
        for (int nt = 0; nt < 4; ++nt) {
            #pragma unroll
            for (int j = 0; j < 4; ++j) {
                float v = acc[nt][j];
                v = (v >= 0.f) ? v : 0.2f * v;
                acc[nt][j] = v;
                if (j < 2) p0 = fmaf(v, v, p0);
                else       p1 = fmaf(v, v, p1);
            }
        }
        p0 += __shfl_xor_sync(0xffffffffu, p0, 1);
        p0 += __shfl_xor_sync(0xffffffffu, p0, 2);
        p1 += __shfl_xor_sync(0xffffffffu, p1, 1);
        p1 += __shfl_xor_sync(0xffffffffu, p1, 2);
        if ((lane & 3) == 0) {
            atomicAdd(rowsum + r0, p0);
            atomicAdd(rowsum + r1, p1);
        }
        __syncthreads();

        // ---- 4) scale + store
        const float inv0 = 1.0f / fmaxf(sqrtf(rowsum[r0]), 1e-12f);
        const float inv1 = 1.0f / fmaxf(sqrtf(rowsum[r1]), 1e-12f);
        float2* out2 = (float2*)out;
        const int g0 = rowBase + r0;
        const int g1 = rowBase + r1;
        const int colh = (n0 + (lane & 3) * 2) >> 1;
        #pragma unroll
        for (int nt = 0; nt < 4; ++nt) {
            int c2 = colh + nt * 4;
            if (g0 < NN)
                out2[(size_t)g0 * 64 + c2] = make_float2(acc[nt][0] * inv0, acc[nt][1] * inv0);
            if (g1 < NN)
                out2[(size_t)g1 * 64 + c2] = make_float2(acc[nt][2] * inv1, acc[nt][3] * inv1);
        }
        __syncthreads();
        if (tid < BM) rowsum[tid] = 0.f;
        // note: rowsum zeroing races nothing — next atomics happen after
        // the aggregate-phase __syncthreads above.
    }
}

// ---------------------------------------------------------------------------
// Launch
// ---------------------------------------------------------------------------
extern "C" void kernel_launch(void* const* d_in, const int* in_sizes, int n_in,
                              void* d_out, int out_size)
{
    const float* ego  = (const float*)d_in[0];
    const float* norm = (const float*)d_in[1];
    const int*   src  = (const int*)d_in[2];
    const int*   dst  = (const int*)d_in[3];
    const float* W1   = (const float*)d_in[4];
    const float* W2   = (const float*)d_in[5];
    float* out = (float*)d_out;

    int*  cnt;   cudaGetSymbolAddress((void**)&cnt,   g_cnt);
    int*  off;   cudaGetSymbolAddress((void**)&off,   g_off);
    int*  cur;   cudaGetSymbolAddress((void**)&cur,   g_cur);
    int*  total; cudaGetSymbolAddress((void**)&total, g_total);
    int2* meta;  cudaGetSymbolAddress((void**)&meta,  g_meta);
    __nv_bfloat16* bhi; cudaGetSymbolAddress((void**)&bhi, g_Bhi);
    __nv_bfloat16* blo; cudaGetSymbolAddress((void**)&blo, g_Blo);

    cudaMemsetAsync(cnt, 0, NN * sizeof(int));
    cudaMemsetAsync(total, 0, sizeof(int));
    hist_kernel<<<(EE + 255) / 256, 256>>>(dst, cnt);
    alloc_kernel<<<(NN + 255) / 256, 256>>>(cnt, off, cur, total);
    scatter_kernel<<<(EE + 255) / 256, 256>>>(src, dst, norm, cur, meta);
    prepB_kernel<<<128, 256>>>(W1, W2, bhi, blo);

    cudaFuncSetAttribute(fused_kernel,
                         cudaFuncAttributeMaxDynamicSharedMemorySize, SM_TOTAL);
    fused_kernel<<<GRID_PERSIST, THREADS, SM_TOTAL>>>(
        (const float4*)ego, off, cnt, meta, out);
}

// round 10
// speedup vs baseline: 1.8174x; 1.0353x over previous
#include <cuda_runtime.h>
#include <cuda_bf16.h>
#include <cstdint>
#include <math.h>

#define NN 100000
#define EE 1000000
#define BM 64
#define THREADS 1024
#define NBLK ((NN + BM - 1) / BM)      // 1563
#define GRID_PERSIST 148

// B (W) padded layout: [256 k][144 n] bf16
#define BP 144
// X padded layout: [64 m][272 k] bf16
#define XP 272

// smem byte offsets
#define SM_B_HI   0
#define SM_B_LO   73728
#define SM_XHI    147456
#define SM_XLO    182272
#define SM_ROWSUM 217088
#define SM_TOTAL  217344

typedef unsigned int u32;
typedef unsigned long long u64;

// Scratch
__device__ int  g_cnt[NN];
__device__ int  g_off[NN];
__device__ int  g_cur[NN];
__device__ int  g_total;
__device__ int2 g_meta[EE];
__device__ __align__(16) __nv_bfloat16 g_Bhi[256 * BP];
__device__ __align__(16) __nv_bfloat16 g_Blo[256 * BP];

// ---------------------------------------------------------------------------
// CSR build
// ---------------------------------------------------------------------------
__global__ void hist_kernel(const int* __restrict__ dst, int* __restrict__ cnt)
{
    int e = blockIdx.x * blockDim.x + threadIdx.x;
    if (e < EE) atomicAdd(&cnt[__ldg(dst + e)], 1);
}

__global__ void alloc_kernel(const int* __restrict__ cnt,
                             int* __restrict__ off,
                             int* __restrict__ cur,
                             int* __restrict__ total)
{
    int i = blockIdx.x * blockDim.x + threadIdx.x;
    if (i < NN) {
        int o = atomicAdd(total, cnt[i]);
        off[i] = o;
        cur[i] = o;
    }
}

__global__ void scatter_kernel(const int* __restrict__ src,
                               const int* __restrict__ dst,
                               const float* __restrict__ norm,
                               int* __restrict__ cur,
                               int2* __restrict__ meta)
{
    int e = blockIdx.x * blockDim.x + threadIdx.x;
    if (e >= EE) return;
    int s = __ldg(src + e);
    int d = __ldg(dst + e);
    float w = __ldg(norm + s) * __ldg(norm + d);
    int pos = atomicAdd(&cur[d], 1);
    meta[pos] = make_int2(s, __float_as_int(w));
}

// ---------------------------------------------------------------------------
// B prep
// ---------------------------------------------------------------------------
__global__ void prepB_kernel(const float* __restrict__ W1,
                             const float* __restrict__ W2,
                             __nv_bfloat16* __restrict__ bhi,
                             __nv_bfloat16* __restrict__ blo)
{
    int idx = blockIdx.x * blockDim.x + threadIdx.x;
    if (idx >= 256 * 128) return;
    int k = idx >> 7;
    int n = idx & 127;
    float v = (k < 128) ? __ldg(W1 + k * 128 + n) : __ldg(W2 + (k - 128) * 128 + n);
    __nv_bfloat16 h = __float2bfloat16(v);
    bhi[k * BP + n] = h;
    blo[k * BP + n] = __float2bfloat16(v - __bfloat162float(h));
}

// ---------------------------------------------------------------------------
// PTX helpers
// ---------------------------------------------------------------------------
__device__ __forceinline__ u32 smem_u32_of(const void* p)
{
    u32 a;
    asm("{ .reg .u64 t; cvta.to.shared.u64 t, %1; cvt.u32.u64 %0, t; }"
        : "=r"(a) : "l"(p));
    return a;
}
__device__ __forceinline__ void cp_async16(u32 dst, const void* src)
{
    asm volatile("cp.async.cg.shared.global [%0], [%1], 16;"
                 :: "r"(dst), "l"(src) : "memory");
}
__device__ __forceinline__ void ldsm_x4(u32& r0, u32& r1, u32& r2, u32& r3, u32 addr)
{
    asm volatile("ldmatrix.sync.aligned.m8n8.x4.shared.b16 {%0,%1,%2,%3}, [%4];"
                 : "=r"(r0), "=r"(r1), "=r"(r2), "=r"(r3) : "r"(addr));
}
__device__ __forceinline__ void ldsm_x4_t(u32& r0, u32& r1, u32& r2, u32& r3, u32 addr)
{
    asm volatile("ldmatrix.sync.aligned.m8n8.x4.trans.shared.b16 {%0,%1,%2,%3}, [%4];"
                 : "=r"(r0), "=r"(r1), "=r"(r2), "=r"(r3) : "r"(addr));
}
__device__ __forceinline__ void mma16816(float* c, u32 a0, u32 a1, u32 a2, u32 a3,
                                         u32 b0, u32 b1)
{
    asm volatile(
        "mma.sync.aligned.m16n8k16.row.col.f32.bf16.bf16.f32 "
        "{%0,%1,%2,%3}, {%4,%5,%6,%7}, {%8,%9}, {%0,%1,%2,%3};"
        : "+f"(c[0]), "+f"(c[1]), "+f"(c[2]), "+f"(c[3])
        : "r"(a0), "r"(a1), "r"(a2), "r"(a3), "r"(b0), "r"(b1));
}
__device__ __forceinline__ u32 pack_hi(float x, float y)
{
    unsigned short b0 = __bfloat16_as_ushort(__float2bfloat16(x));
    unsigned short b1 = __bfloat16_as_ushort(__float2bfloat16(y));
    return (u32)b0 | ((u32)b1 << 16);
}
__device__ __forceinline__ u32 pack_lo(float x, float y)
{
    float hx = __bfloat162float(__float2bfloat16(x));
    float hy = __bfloat162float(__float2bfloat16(y));
    unsigned short b0 = __bfloat16_as_ushort(__float2bfloat16(x - hx));
    unsigned short b1 = __bfloat16_as_ushort(__float2bfloat16(y - hy));
    return (u32)b0 | ((u32)b1 << 16);
}

// ---------------------------------------------------------------------------
// Persistent fused kernel (1024 threads): load B once, loop over tiles:
// aggregate (2 nodes/warp) -> Xhi/Xlo -> mma.sync split-2 -> epilogue
// ---------------------------------------------------------------------------
__global__ void __launch_bounds__(THREADS, 1)
fused_kernel(const float4* __restrict__ ego,
             const int*   __restrict__ off,
             const int*   __restrict__ cnt,
             const int2*  __restrict__ meta,
             float*       __restrict__ out)
{
    extern __shared__ char smem[];
    const u32 smem_base = smem_u32_of(smem);
    float* rowsum = (float*)(smem + SM_ROWSUM);

    const int tid  = threadIdx.x;
    const int lane = tid & 31;
    const int warp = tid >> 5;

    // ---- 0) one-time: load Bhi/Blo into smem
    {
        const char* shi = (const char*)g_Bhi;
        const char* slo = (const char*)g_Blo;
        #pragma unroll
        for (int i = 0; i < 5; ++i) {
            int m = tid + i * THREADS;
            if (m < 4608) {
                cp_async16(smem_base + SM_B_HI + m * 16, shi + m * 16);
                cp_async16(smem_base + SM_B_LO + m * 16, slo + m * 16);
            }
        }
        asm volatile("cp.async.commit_group;" ::: "memory");
        asm volatile("cp.async.wait_group 0;" ::: "memory");
    }
    if (tid < BM) rowsum[tid] = 0.f;
    __syncthreads();

    // GEMM constants: warp grid 4m x 8n; warp tile 16m x 16n
    const int m0 = (warp >> 3) * 16;
    const int n0 = (warp & 7) * 16;
    const u32 a_row = m0 + (lane & 15);
    const u32 a_col = (lane >> 4) * 8;
    const u32 aHiBase = smem_base + SM_XHI + a_row * (XP * 2) + a_col * 2;
    const u32 aLoBase = smem_base + SM_XLO + a_row * (XP * 2) + a_col * 2;
    const u32 b_krow = (lane & 7) + ((lane >> 3) & 1) * 8;
    const u32 b_ncol = (lane >> 4) * 8;
    const u32 bHiBase = smem_base + SM_B_HI + b_krow * (BP * 2) + (n0 + b_ncol) * 2;
    const u32 bLoBase = smem_base + SM_B_LO + b_krow * (BP * 2) + (n0 + b_ncol) * 2;
    const int r0 = m0 + (lane >> 2);
    const int r1 = r0 + 8;

    for (int tile = blockIdx.x; tile < NBLK; tile += GRID_PERSIST) {
        const int rowBase = tile * BM;

        // ---- 1) aggregate 2 nodes per warp -> Xhi/Xlo smem (bf16)
        #pragma unroll
        for (int q = 0; q < 2; ++q) {
            int r = warp * 2 + q;
            int node = rowBase + r;
            bool valid = node < NN;

            float4 hd = valid ? __ldg(ego + (size_t)node * 32 + lane)
                              : make_float4(0.f, 0.f, 0.f, 0.f);
            float4 a = hd;
            float4 b = make_float4(0.f, 0.f, 0.f, 0.f);

            int n  = valid ? __ldg(cnt + node) : 0;
            int e0 = valid ? __ldg(off + node) : 0;

            for (int c = 0; c < n; c += 32) {
                int lim = min(32, n - c);
                int2 mm = (lane < lim) ? __ldg(meta + e0 + c + lane) : make_int2(0, 0);
                int j = 0;
                for (; j + 4 <= lim; j += 4) {
                    int   s0 = __shfl_sync(0xffffffffu, mm.x, j + 0);
                    int   s1 = __shfl_sync(0xffffffffu, mm.x, j + 1);
                    int   s2 = __shfl_sync(0xffffffffu, mm.x, j + 2);
                    int   s3 = __shfl_sync(0xffffffffu, mm.x, j + 3);
                    float w0 = __int_as_float(__shfl_sync(0xffffffffu, mm.y, j + 0));
                    float w1 = __int_as_float(__shfl_sync(0xffffffffu, mm.y, j + 1));
                    float w2 = __int_as_float(__shfl_sync(0xffffffffu, mm.y, j + 2));
                    float w3 = __int_as_float(__shfl_sync(0xffffffffu, mm.y, j + 3));
                    float4 h0 = __ldg(ego + (size_t)s0 * 32 + lane);
                    float4 h1 = __ldg(ego + (size_t)s1 * 32 + lane);
                    float4 h2 = __ldg(ego + (size_t)s2 * 32 + lane);
                    float4 h3 = __ldg(ego + (size_t)s3 * 32 + lane);
                    float t;
                    t = w0 * h0.x; a.x += t; b.x = fmaf(t, hd.x, b.x);
                    t = w0 * h0.y; a.y += t; b.y = fmaf(t, hd.y, b.y);
                    t = w0 * h0.z; a.z += t; b.z = fmaf(t, hd.z, b.z);
                    t = w0 * h0.w; a.w += t; b.w = fmaf(t, hd.w, b.w);
                    t = w1 * h1.x; a.x += t; b.x = fmaf(t, hd.x, b.x);
                    t = w1 * h1.y; a.y += t; b.y = fmaf(t, hd.y, b.y);
                    t = w1 * h1.z; a.z += t; b.z = fmaf(t, hd.z, b.z);
                    t = w1 * h1.w; a.w += t; b.w = fmaf(t, hd.w, b.w);
                    t = w2 * h2.x; a.x += t; b.x = fmaf(t, hd.x, b.x);
                    t = w2 * h2.y; a.y += t; b.y = fmaf(t, hd.y, b.y);
                    t = w2 * h2.z; a.z += t; b.z = fmaf(t, hd.z, b.z);
                    t = w2 * h2.w; a.w += t; b.w = fmaf(t, hd.w, b.w);
                    t = w3 * h3.x; a.x += t; b.x = fmaf(t, hd.x, b.x);
                    t = w3 * h3.y; a.y += t; b.y = fmaf(t, hd.y, b.y);
                    t = w3 * h3.z; a.z += t; b.z = fmaf(t, hd.z, b.z);
                    t = w3 * h3.w; a.w += t; b.w = fmaf(t, hd.w, b.w);
                }
                for (; j < lim; ++j) {
                    int   s0 = __shfl_sync(0xffffffffu, mm.x, j);
                    float w0 = __int_as_float(__shfl_sync(0xffffffffu, mm.y, j));
                    float4 h0 = __ldg(ego + (size_t)s0 * 32 + lane);
                    float t;
                    t = w0 * h0.x; a.x += t; b.x = fmaf(t, hd.x, b.x);
                    t = w0 * h0.y; a.y += t; b.y = fmaf(t, hd.y, b.y);
                    t = w0 * h0.z; a.z += t; b.z = fmaf(t, hd.z, b.z);
                    t = w0 * h0.w; a.w += t; b.w = fmaf(t, hd.w, b.w);
                }
            }

            u32* xh = (u32*)(smem + SM_XHI + (size_t)r * (XP * 2));
            u32* xl = (u32*)(smem + SM_XLO + (size_t)r * (XP * 2));
            xh[lane * 2 + 0]  = pack_hi(a.x, a.y);
            xh[lane * 2 + 1]  = pack_hi(a.z, a.w);
            xh[64 + lane * 2] = pack_hi(b.x, b.y);
            xh[65 + lane * 2] = pack_hi(b.z, b.w);
            xl[lane * 2 + 0]  = pack_lo(a.x, a.y);
            xl[lane * 2 + 1]  = pack_lo(a.z, a.w);
            xl[64 + lane * 2] = pack_lo(b.x, b.y);
            xl[65 + lane * 2] = pack_lo(b.z, b.w);
        }
        __syncthreads();

        // ---- 2) GEMM: warp tile 16m x 16n; K=256, split-2
        float acc[2][4];
        #pragma unroll
        for (int i = 0; i < 2; ++i)
            #pragma unroll
            for (int j = 0; j < 4; ++j) acc[i][j] = 0.f;

        #pragma unroll 4
        for (int ks = 0; ks < 16; ++ks) {
            const u32 kOffA = ks * 32;
            const u32 kOffB = ks * 16 * (BP * 2);
            u32 ah0, ah1, ah2, ah3, al0, al1, al2, al3;
            ldsm_x4(ah0, ah1, ah2, ah3, aHiBase + kOffA);
            ldsm_x4(al0, al1, al2, al3, aLoBase + kOffA);

            u32 bh0, bh1, bh2, bh3, bl0, bl1, bl2, bl3;
            ldsm_x4_t(bh0, bh1, bh2, bh3, bHiBase + kOffB);
            ldsm_x4_t(bl0, bl1, bl2, bl3, bLoBase + kOffB);
            mma16816(acc[0], ah0, ah1, ah2, ah3, bh0, bh1);
            mma16816(acc[0], ah0, ah1, ah2, ah3, bl0, bl1);
            mma16816(acc[0], al0, al1, al2, al3, bh0, bh1);
            mma16816(acc[1], ah0, ah1, ah2, ah3, bh2, bh3);
            mma16816(acc[1], ah0, ah1, ah2, ah3, bl2, bl3);
            mma16816(acc[1], al0, al1, al2, al3, bh2, bh3);
        }

        // ---- 3) leaky relu + per-row sumsq partials
        float p0 = 0.f, p1 = 0.f;
        #pragma unroll
        for (int nt = 0; nt < 2; ++nt) {
            #pragma unroll
            for (int j = 0; j < 4; ++j) {
                float v = acc[nt][j];
                v = (v >= 0.f) ? v : 0.2f * v;
                acc[nt][j] = v;
                if (j < 2) p0 = fmaf(v, v, p0);
                else       p1 = fmaf(v, v, p1);
            }
        }
        p0 += __shfl_xor_sync(0xffffffffu, p0, 1);
        p0 += __shfl_xor_sync(0xffffffffu, p0, 2);
        p1 += __shfl_xor_sync(0xffffffffu, p1, 1);
        p1 += __shfl_xor_sync(0xffffffffu, p1, 2);
        if ((lane & 3) == 0) {
            atomicAdd(rowsum + r0, p0);
            atomicAdd(rowsum + r1, p1);
        }
        __syncthreads();

        // ---- 4) scale + store
        const float inv0 = 1.0f / fmaxf(sqrtf(rowsum[r0]), 1e-12f);
        const float inv1 = 1.0f / fmaxf(sqrtf(rowsum[r1]), 1e-12f);
        float2* out2 = (float2*)out;
        const int g0 = rowBase + r0;
        const int g1 = rowBase + r1;
        const int colh = (n0 + (lane & 3) * 2) >> 1;
        #pragma unroll
        for (int nt = 0; nt < 2; ++nt) {
            int c2 = colh + nt * 4;
            if (g0 < NN)
                out2[(size_t)g0 * 64 + c2] = make_float2(acc[nt][0] * inv0, acc[nt][1] * inv0);
            if (g1 < NN)
                out2[(size_t)g1 * 64 + c2] = make_float2(acc[nt][2] * inv1, acc[nt][3] * inv1);
        }
        __syncthreads();
        if (tid < BM) rowsum[tid] = 0.f;
    }
}

// ---------------------------------------------------------------------------
// Launch
// ---------------------------------------------------------------------------
extern "C" void kernel_launch(void* const* d_in, const int* in_sizes, int n_in,
                              void* d_out, int out_size)
{
    const float* ego  = (const float*)d_in[0];
    const float* norm = (const float*)d_in[1];
    const int*   src  = (const int*)d_in[2];
    const int*   dst  = (const int*)d_in[3];
    const float* W1   = (const float*)d_in[4];
    const float* W2   = (const float*)d_in[5];
    float* out = (float*)d_out;

    int*  cnt;   cudaGetSymbolAddress((void**)&cnt,   g_cnt);
    int*  off;   cudaGetSymbolAddress((void**)&off,   g_off);
    int*  cur;   cudaGetSymbolAddress((void**)&cur,   g_cur);
    int*  total; cudaGetSymbolAddress((void**)&total, g_total);
    int2* meta;  cudaGetSymbolAddress((void**)&meta,  g_meta);
    __nv_bfloat16* bhi; cudaGetSymbolAddress((void**)&bhi, g_Bhi);
    __nv_bfloat16* blo; cudaGetSymbolAddress((void**)&blo, g_Blo);

    cudaMemsetAsync(cnt, 0, NN * sizeof(int));
    cudaMemsetAsync(total, 0, sizeof(int));
    hist_kernel<<<(EE + 255) / 256, 256>>>(dst, cnt);
    alloc_kernel<<<(NN + 255) / 256, 256>>>(cnt, off, cur, total);
    scatter_kernel<<<(EE + 255) / 256, 256>>>(src, dst, norm, cur, meta);
    prepB_kernel<<<128, 256>>>(W1, W2, bhi, blo);

    cudaFuncSetAttribute(fused_kernel,
                         cudaFuncAttributeMaxDynamicSharedMemorySize, SM_TOTAL);
    fused_kernel<<<GRID_PERSIST, THREADS, SM_TOTAL>>>(
        (const float4*)ego, off, cnt, meta, out);
}